// round 1
// baseline (speedup 1.0000x reference)
#include <cuda_runtime.h>

#define NPW      2048      // 65536 points / 32 bits
#define PTOT_MAX 512
#define BMAX     8
#define MAXP     128

__device__ unsigned g_pc_bits[PTOT_MAX * NPW];   // 4 MB bitmask: proposal x point
__device__ unsigned g_ref_bits[BMAX * NPW];      // per-scene reference cluster bitmask
__device__ int      g_ref_sum[BMAX];
__device__ int      g_offs[BMAX + 1];
__device__ float    g_iou[PTOT_MAX];

// K1: zero proposal bitmasks, ref sums, and the (poisoned) output buffer
__global__ void k_zero(float* out, int out_n, int pc_words) {
    int tid = blockIdx.x * blockDim.x + threadIdx.x;
    int stride = gridDim.x * blockDim.x;
    for (int w = tid; w < pc_words; w += stride) g_pc_bits[w] = 0u;
    for (int w = tid; w < out_n; w += stride) out[w] = 0.0f;
    if (tid < BMAX) g_ref_sum[tid] = 0;
}

// K2: build per-scene reference bitmask (instance_labels == object_id), its popcount,
//     and the proposal offsets (cumsum) from one thread.
__global__ void k_ref(const int* __restrict__ labels, const int* __restrict__ object_id,
                      const int* __restrict__ pes, int B, int npoint, int npw) {
    int w = blockIdx.x * blockDim.x + threadIdx.x;
    if (w == 0) {
        g_offs[0] = 0;
        for (int b = 0; b < B; b++) g_offs[b + 1] = g_offs[b] + pes[b];
    }
    int total = B * npw;
    if (w >= total) return;
    int b = w / npw, k = w - b * npw;
    int oid = object_id[b];
    int base = b * npoint + k * 32;
    int lim = npoint - k * 32; if (lim > 32) lim = 32;
    unsigned bits = 0;
    #pragma unroll 4
    for (int t = 0; t < lim; t++)
        bits |= (labels[base + t] == oid) ? (1u << t) : 0u;
    g_ref_bits[b * NPW + k] = bits;
    unsigned c = __popc(bits);
    // warp-aggregate before the atomic (warps may straddle scenes only at b boundaries,
    // which are NPW=2048-aligned, so a warp is always within one scene)
    c = __reduce_add_sync(0xffffffffu, c);
    if ((threadIdx.x & 31) == 0) atomicAdd(&g_ref_sum[b], (int)c);
}

// K3: scatter — set bit (pid, j % npoint). RED.OR, no return value.
__global__ void k_scatter(const int2* __restrict__ pidx, int M, int npoint) {
    int i = blockIdx.x * blockDim.x + threadIdx.x;
    if (i >= M) return;
    int2 v = __ldg(&pidx[i]);
    unsigned j = (unsigned)v.y % (unsigned)npoint;
    atomicOr(&g_pc_bits[(size_t)v.x * NPW + (j >> 5)], 1u << (j & 31u));
}

// K4: per-proposal AND-popcount reduction -> IoU
__global__ void k_reduce(int B, int npw) {
    int p = blockIdx.x;
    int b = 0;
    for (int k = 1; k <= B; k++) b += (g_offs[k] <= p) ? 1 : 0;
    if (b >= B) b = B - 1;
    const unsigned* __restrict__ pcrow  = g_pc_bits + (size_t)p * NPW;
    const unsigned* __restrict__ refrow = g_ref_bits + (size_t)b * NPW;
    unsigned cnt = 0, its = 0;
    for (int w = threadIdx.x; w < npw; w += blockDim.x) {
        unsigned v = pcrow[w];
        cnt += __popc(v);
        its += __popc(v & refrow[w]);
    }
    cnt = __reduce_add_sync(0xffffffffu, cnt);
    its = __reduce_add_sync(0xffffffffu, its);
    __shared__ unsigned sc[8], si[8];
    int warp = threadIdx.x >> 5;
    if ((threadIdx.x & 31) == 0) { sc[warp] = cnt; si[warp] = its; }
    __syncthreads();
    if (threadIdx.x == 0) {
        unsigned Ct = 0, It = 0;
        int nwarp = blockDim.x >> 5;
        for (int w2 = 0; w2 < nwarp; w2++) { Ct += sc[w2]; It += si[w2]; }
        float inter = (float)It;
        float uni = (float)Ct + (float)g_ref_sum[b] - inter;
        g_iou[p] = (uni > 0.0f) ? inter / fmaxf(uni, 1.0f) : 0.0f;
    }
}

// K5: per-batch argmax + all output writes.
// Output layout (f32 flat): [B*MAXP*C clus_feats | B*C select_feats | B sel_idx | B+1 offsets | B good]
__global__ void k_final(const float* __restrict__ feats, const int* __restrict__ pes,
                        int B, int PTOT, int C, float* __restrict__ out) {
    __shared__ int   s_best[BMAX];
    __shared__ float s_max[BMAX];
    int tid = threadIdx.x;
    if (tid < B) {
        int lo = g_offs[tid], hi = g_offs[tid + 1];
        int best = -1; float mx = -1.0f;
        for (int p = lo; p < hi; p++) {
            float v = g_iou[p];
            if (v > mx) { mx = v; best = p; }   // strict >: first max wins (matches argmax)
        }
        s_best[tid] = (pes[tid] > 0) ? best : -1;
        s_max[tid] = mx;
    }
    __syncthreads();
    int clus_n   = B * MAXP * C;
    int sf_off   = clus_n;
    int spi_off  = sf_off + B * C;
    int offs_off = spi_off + B;
    int good_off = offs_off + B + 1;
    // clus_feats_batch[b, slot] = feats[p], slot = p - offs[b]
    for (int idx = tid; idx < PTOT * C; idx += blockDim.x) {
        int p = idx / C, c = idx - p * C;
        int b = 0;
        for (int k = 1; k <= B; k++) b += (g_offs[k] <= p) ? 1 : 0;
        if (b >= B) b = B - 1;
        int slot = p - g_offs[b];
        if (slot < MAXP)
            out[(size_t)b * MAXP * C + (size_t)slot * C + c] = feats[idx];
    }
    // select_feats
    for (int idx = tid; idx < B * C; idx += blockDim.x) {
        int b = idx / C, c = idx - b * C;
        int sel = s_best[b];
        out[sf_off + idx] = (sel >= 0) ? feats[(size_t)sel * C + c] : 0.0f;
    }
    if (tid < B)  out[spi_off + tid]  = (float)s_best[tid];
    if (tid <= B) out[offs_off + tid] = (float)g_offs[tid];
    if (tid < B)  out[good_off + tid] = ((s_max[tid] > 0.2f) && (pes[tid] > 0)) ? 1.0f : 0.0f;
}

extern "C" void kernel_launch(void* const* d_in, const int* in_sizes, int n_in,
                              void* d_out, int out_size) {
    const int*   pidx   = (const int*)d_in[0];   // [M,2] int32
    const int*   pes    = (const int*)d_in[1];   // [B] int32
    const int*   labels = (const int*)d_in[2];   // [B*npoint] int32
    const int*   oid    = (const int*)d_in[3];   // [B] int32
    const float* feats  = (const float*)d_in[4]; // [PTOT, C] f32
    float* out = (float*)d_out;

    int M       = in_sizes[0] / 2;
    int B       = in_sizes[1];
    int n_total = in_sizes[2];
    int npoint  = n_total / B;
    int C       = 32;
    int PTOT    = in_sizes[4] / C;
    int npw     = (npoint + 31) / 32;

    k_zero<<<2048, 256>>>(out, out_size, PTOT * NPW);
    k_ref<<<(B * npw + 255) / 256, 256>>>(labels, oid, pes, B, npoint, npw);
    k_scatter<<<(M + 255) / 256, 256>>>((const int2*)pidx, M, npoint);
    k_reduce<<<PTOT, 256>>>(B, npw);
    k_final<<<1, 256>>>(feats, pes, B, PTOT, C, out);
}

// round 2
// speedup vs baseline: 1.1264x; 1.1264x over previous
#include <cuda_runtime.h>

#define NPW      2048      // 65536 points / 32 bits
#define PTOT_MAX 512
#define BMAX     8
#define MAXP     128

__device__ unsigned g_pc_bits[PTOT_MAX * NPW];   // 4 MB bitmask: proposal x point
__device__ unsigned g_ref_bits[BMAX * NPW];      // per-scene reference cluster bitmask
__device__ int      g_ref_sum[BMAX];
__device__ int      g_offs[BMAX + 1];
__device__ float    g_iou[PTOT_MAX];
__device__ int      g_ctr;

// K_init: build per-scene reference bitmask + popcount + offsets + counter reset.
// (g_pc_bits is zeroed by a cudaMemsetAsync node before this.)
__global__ void k_init(const int* __restrict__ labels, const int* __restrict__ object_id,
                       const int* __restrict__ pes, int B, int npoint, int npw) {
    int w = blockIdx.x * blockDim.x + threadIdx.x;
    if (w == 0) {
        g_offs[0] = 0;
        for (int b = 0; b < B; b++) g_offs[b + 1] = g_offs[b] + pes[b];
        g_ctr = 0;
    }
    if (w < BMAX) g_ref_sum[w] = 0;
    int total = B * npw;
    if (w >= total) return;
    int b = w / npw, k = w - b * npw;
    int oid = __ldg(&object_id[b]);
    int base = b * npoint + k * 32;
    int lim = npoint - k * 32; if (lim > 32) lim = 32;
    unsigned bits = 0;
    #pragma unroll 4
    for (int t = 0; t < lim; t++)
        bits |= (__ldg(&labels[base + t]) == oid) ? (1u << t) : 0u;
    g_ref_bits[b * NPW + k] = bits;
    unsigned c = __popc(bits);
    // b boundaries are NPW=2048-aligned -> a warp never straddles scenes
    c = __reduce_add_sync(0xffffffffu, c);
    if ((threadIdx.x & 31) == 0) atomicAdd(&g_ref_sum[b], (int)c);
}

// K_scatter: set bit (pid, j % npoint). 2 pairs per thread via int4.
__global__ void k_scatter(const int4* __restrict__ pidx2, int M2, int npoint) {
    int i = blockIdx.x * blockDim.x + threadIdx.x;
    if (i >= M2) return;
    int4 v = __ldg(&pidx2[i]);
    unsigned j0 = (unsigned)v.y % (unsigned)npoint;
    unsigned j1 = (unsigned)v.w % (unsigned)npoint;
    atomicOr(&g_pc_bits[(size_t)v.x * NPW + (j0 >> 5)], 1u << (j0 & 31u));
    atomicOr(&g_pc_bits[(size_t)v.z * NPW + (j1 >> 5)], 1u << (j1 & 31u));
}

// tail pairs (if M is odd)
__global__ void k_scatter_tail(const int2* __restrict__ pidx, int start, int M, int npoint) {
    int i = start + blockIdx.x * blockDim.x + threadIdx.x;
    if (i >= M) return;
    int2 v = __ldg(&pidx[i]);
    unsigned j = (unsigned)v.y % (unsigned)npoint;
    atomicOr(&g_pc_bits[(size_t)v.x * NPW + (j >> 5)], 1u << (j & 31u));
}

// K_reduce_final: warp per proposal (uint4 loads, MLP=16), then the LAST block
// performs the argmax + all output writes.
// Output layout (f32): [B*MAXP*C clus_feats | B*C select_feats | B sel_idx | B+1 offsets | B good]
__global__ void k_reduce_final(int B, int npw, int PTOT, int C,
                               const float* __restrict__ feats,
                               const int* __restrict__ pes,
                               float* __restrict__ out) {
    int lane = threadIdx.x & 31;
    int gw = (blockIdx.x * blockDim.x + threadIdx.x) >> 5;  // proposal id
    if (gw < PTOT) {
        int p = gw;
        int b = 0;
        #pragma unroll
        for (int k = 1; k <= BMAX; k++) b += (k <= B && g_offs[k] <= p) ? 1 : 0;
        if (b >= B) b = B - 1;
        const uint4* __restrict__ pcrow  = (const uint4*)(g_pc_bits + (size_t)p * NPW);
        const uint4* __restrict__ refrow = (const uint4*)(g_ref_bits + (size_t)b * NPW);
        int nq = npw >> 2;                 // uint4 chunks in a row (512)
        unsigned cnt = 0, its = 0;
        #pragma unroll 16
        for (int w = lane; w < nq; w += 32) {
            uint4 v = __ldg(&pcrow[w]);
            uint4 r = __ldg(&refrow[w]);
            cnt += __popc(v.x) + __popc(v.y) + __popc(v.z) + __popc(v.w);
            its += __popc(v.x & r.x) + __popc(v.y & r.y)
                 + __popc(v.z & r.z) + __popc(v.w & r.w);
        }
        cnt = __reduce_add_sync(0xffffffffu, cnt);
        its = __reduce_add_sync(0xffffffffu, its);
        if (lane == 0) {
            float inter = (float)its;
            float uni = (float)cnt + (float)g_ref_sum[b] - inter;
            g_iou[p] = (uni > 0.0f) ? inter / fmaxf(uni, 1.0f) : 0.0f;
        }
    }
    // ---- last-block-done epilogue ----
    __syncthreads();
    __shared__ int s_last;
    if (threadIdx.x == 0) {
        __threadfence();
        s_last = (atomicAdd(&g_ctr, 1) == (int)gridDim.x - 1) ? 1 : 0;
    }
    __syncthreads();
    if (!s_last) return;

    __shared__ int   s_best[BMAX];
    __shared__ float s_max[BMAX];
    int tid = threadIdx.x;
    if (tid < B) {
        int lo = g_offs[tid], hi = g_offs[tid + 1];
        int best = -1; float mx = -1.0f;
        for (int p2 = lo; p2 < hi; p2++) {
            float v = g_iou[p2];
            if (v > mx) { mx = v; best = p2; }    // strict >: first max wins
        }
        s_best[tid] = (__ldg(&pes[tid]) > 0) ? best : -1;
        s_max[tid] = mx;
    }
    __syncthreads();
    int clus_n   = B * MAXP * C;
    int sf_off   = clus_n;
    int spi_off  = sf_off + B * C;
    int offs_off = spi_off + B;
    int good_off = offs_off + B + 1;
    // clus_feats_batch: write ALL entries (zeros where no proposal lands)
    int mc = MAXP * C;
    for (int idx = tid; idx < clus_n; idx += blockDim.x) {
        int b = idx / mc, rem = idx - b * mc;
        int slot = rem / C, c = rem - slot * C;
        int p = g_offs[b] + slot;
        float v = (p < g_offs[b + 1]) ? __ldg(&feats[(size_t)p * C + c]) : 0.0f;
        out[idx] = v;
    }
    for (int idx = tid; idx < B * C; idx += blockDim.x) {
        int b = idx / C, c = idx - b * C;
        int sel = s_best[b];
        out[sf_off + idx] = (sel >= 0) ? __ldg(&feats[(size_t)sel * C + c]) : 0.0f;
    }
    if (tid < B)  out[spi_off + tid]  = (float)s_best[tid];
    if (tid <= B) out[offs_off + tid] = (float)g_offs[tid];
    if (tid < B)  out[good_off + tid] = ((s_max[tid] > 0.2f) && (__ldg(&pes[tid]) > 0)) ? 1.0f : 0.0f;
}

extern "C" void kernel_launch(void* const* d_in, const int* in_sizes, int n_in,
                              void* d_out, int out_size) {
    const int*   pidx   = (const int*)d_in[0];   // [M,2] int32
    const int*   pes    = (const int*)d_in[1];   // [B] int32
    const int*   labels = (const int*)d_in[2];   // [B*npoint] int32
    const int*   oid    = (const int*)d_in[3];   // [B] int32
    const float* feats  = (const float*)d_in[4]; // [PTOT, C] f32
    float* out = (float*)d_out;

    int M       = in_sizes[0] / 2;
    int B       = in_sizes[1];
    int n_total = in_sizes[2];
    int npoint  = n_total / B;
    int C       = 32;
    int PTOT    = in_sizes[4] / C;
    int npw     = (npoint + 31) / 32;

    // zero the proposal bitmask via driver memset (fast, one graph node)
    void* pc_ptr = nullptr;
    cudaGetSymbolAddress(&pc_ptr, g_pc_bits);
    cudaMemsetAsync(pc_ptr, 0, (size_t)PTOT * NPW * sizeof(unsigned), 0);

    k_init<<<(B * npw + 255) / 256, 256>>>(labels, oid, pes, B, npoint, npw);

    int M2 = M / 2;
    if (M2 > 0)
        k_scatter<<<(M2 + 255) / 256, 256>>>((const int4*)pidx, M2, npoint);
    if (M & 1)
        k_scatter_tail<<<1, 32>>>((const int2*)pidx, M2 * 2, M, npoint);

    int nwarps = PTOT;                 // one warp per proposal
    int threads = 256;
    int grid = (nwarps * 32 + threads - 1) / threads;
    k_reduce_final<<<grid, threads>>>(B, npw, PTOT, C, feats, pes, out);
}